// round 1
// baseline (speedup 1.0000x reference)
#include <cuda_runtime.h>
#include <cuda_bf16.h>

// StimulusLayer: dist[b,o] = max_i |x[b,i] - stim[o,i]| (Chebyshev),
// out[b,o] = state[b,o]*0.95 + sigmoid((a[o]-dist)*bvec[o]).
// B=128, I=256, O=4096. Compute-bound: ~2-3 scalar FP inst per (b,o,i).
//
// Tiling: block tile 16(b) x 32(o), 64 threads, thread tile 4b x 2o,
// k vectorized by float4 through padded shared memory.

#define B_DIM 128
#define I_DIM 256
#define O_DIM 4096
#define KC    64          // k-chunk staged in smem
#define PITCH 68          // 64 + 4 pad floats; row pitch (17 float4s, odd -> bank spread)

__global__ __launch_bounds__(64, 16)
void stimulus_kernel(const float* __restrict__ x,
                     const float* __restrict__ stim,
                     const float* __restrict__ a,
                     const float* __restrict__ bvec,
                     const float* __restrict__ state,
                     float* __restrict__ out)
{
    __shared__ float xs[16 * PITCH];   // 16 b-rows x 64 k (+pad)
    __shared__ float ss[32 * PITCH];   // 32 o-rows x 64 k (+pad)

    const int tid = threadIdx.x;           // 0..63
    const int tb  = tid >> 4;              // 0..3  (b group)
    const int to  = tid & 15;              // 0..15 (o group; lanes 0-15 -> consecutive o for coalesced stores)

    const int b0 = blockIdx.y * 16;
    const int o0 = blockIdx.x * 32;

    const float4* __restrict__ x4 = (const float4*)x;
    const float4* __restrict__ s4 = (const float4*)stim;

    float m[4][2];
    #pragma unroll
    for (int jb = 0; jb < 4; jb++)
        #pragma unroll
        for (int jo = 0; jo < 2; jo++)
            m[jb][jo] = 0.0f;              // |d| >= 0, safe init

    for (int kc = 0; kc < I_DIM / KC; kc++) {
        // stage x chunk: 16 rows x 16 float4 = 256 float4, 4 per thread
        #pragma unroll
        for (int t = 0; t < 4; t++) {
            int idx = tid + t * 64;        // 0..255
            int row = idx >> 4;
            int col = idx & 15;
            float4 v = x4[(b0 + row) * (I_DIM / 4) + kc * (KC / 4) + col];
            *(float4*)&xs[row * PITCH + col * 4] = v;
        }
        // stage stim chunk: 32 rows x 16 float4 = 512 float4, 8 per thread
        #pragma unroll
        for (int t = 0; t < 8; t++) {
            int idx = tid + t * 64;        // 0..511
            int row = idx >> 4;
            int col = idx & 15;
            float4 v = s4[(o0 + row) * (I_DIM / 4) + kc * (KC / 4) + col];
            *(float4*)&ss[row * PITCH + col * 4] = v;
        }
        __syncthreads();

        #pragma unroll 4
        for (int k4 = 0; k4 < KC / 4; k4++) {
            float4 xv[4];
            float4 sv[2];
            #pragma unroll
            for (int jb = 0; jb < 4; jb++)
                xv[jb] = *(const float4*)&xs[(tb + 4 * jb) * PITCH + k4 * 4];
            #pragma unroll
            for (int jo = 0; jo < 2; jo++)
                sv[jo] = *(const float4*)&ss[(to + 16 * jo) * PITCH + k4 * 4];

            #pragma unroll
            for (int jb = 0; jb < 4; jb++) {
                #pragma unroll
                for (int jo = 0; jo < 2; jo++) {
                    float mm = m[jb][jo];
                    mm = fmaxf(mm, fabsf(xv[jb].x - sv[jo].x));
                    mm = fmaxf(mm, fabsf(xv[jb].y - sv[jo].y));
                    mm = fmaxf(mm, fabsf(xv[jb].z - sv[jo].z));
                    mm = fmaxf(mm, fabsf(xv[jb].w - sv[jo].w));
                    m[jb][jo] = mm;
                }
            }
        }
        __syncthreads();
    }

    // epilogue: sigmoid((a - dist) * bvec), decayed state update
    #pragma unroll
    for (int jo = 0; jo < 2; jo++) {
        int o = o0 + to + 16 * jo;
        float av = a[o];
        float bv = bvec[o];
        #pragma unroll
        for (int jb = 0; jb < 4; jb++) {
            int b = b0 + tb + 4 * jb;
            float z   = (av - m[jb][jo]) * bv;
            float val = 1.0f / (1.0f + __expf(-z));
            long idx  = (long)b * O_DIM + o;
            out[idx]  = state[idx] * 0.95f + val;
        }
    }
}

extern "C" void kernel_launch(void* const* d_in, const int* in_sizes, int n_in,
                              void* d_out, int out_size)
{
    const float* x     = (const float*)d_in[0];   // (128, 256)
    const float* stim  = (const float*)d_in[1];   // (4096, 256)
    const float* a     = (const float*)d_in[2];   // (4096,)
    const float* bvec  = (const float*)d_in[3];   // (4096,)
    const float* state = (const float*)d_in[4];   // (128, 4096)
    float* out = (float*)d_out;                   // (128, 4096)

    dim3 grid(O_DIM / 32, B_DIM / 16);            // 128 x 8 = 1024 blocks
    stimulus_kernel<<<grid, 64>>>(x, stim, a, bvec, state, out);
}